// round 1
// baseline (speedup 1.0000x reference)
#include <cuda_runtime.h>

#define NQ      10000
#define D       128
#define NHEADS  8
#define NPOINTS 4
#define HSP     51
#define WSP     102
#define HW      (HSP * WSP)
#define NL      50
#define HD      16
#define TPB     256
#define GRID    296

// Scratch (device globals; no allocation allowed)
__device__ float g_proj[NHEADS * HW * HD];   // [head][spatial][hd-chan], 2.66 MB
__device__ float g_wp[D];                    // W_out @ W_proj (128-vector)

// ---------------------------------------------------------------------------
// Kernel A: value projection  v = value @ W_val + b_val, stored head-major
// ---------------------------------------------------------------------------
__global__ void val_proj_kernel(const float* __restrict__ value,
                                const float* __restrict__ W_val,
                                const float* __restrict__ b_val) {
    __shared__ float vrow[D];
    int d = threadIdx.x;            // 0..127 (output channel)
    int row0 = blockIdx.x * 64;
    float bv = b_val[d];
    for (int r = 0; r < 64; r++) {
        int s = row0 + r;
        if (s >= HW) break;         // uniform across block
        __syncthreads();
        vrow[d] = value[s * D + d];
        __syncthreads();
        float acc = bv;
#pragma unroll 8
        for (int k = 0; k < D; k++)
            acc = fmaf(vrow[k], W_val[k * D + d], acc);
        g_proj[(d >> 4) * (HW * HD) + s * HD + (d & 15)] = acc;
    }
}

// ---------------------------------------------------------------------------
// Kernel B: Wp[k] = sum_d W_out[k][d] * W_proj[d]
// ---------------------------------------------------------------------------
__global__ void wp_kernel(const float* __restrict__ W_out,
                          const float* __restrict__ W_proj) {
    int k = threadIdx.x;
    float acc = 0.f;
#pragma unroll 8
    for (int dd = 0; dd < D; dd++)
        acc = fmaf(W_out[k * D + dd], W_proj[dd], acc);
    g_wp[k] = acc;
}

// ---------------------------------------------------------------------------
// Tail fill (only if harness output buffer is larger than bev+idx)
// ---------------------------------------------------------------------------
__global__ void fill_zero_kernel(float* __restrict__ p, int n) {
    int i = blockIdx.x * 256 + threadIdx.x;
    if (i < n) p[i] = 0.f;
}

// ---------------------------------------------------------------------------
// Kernel C: main fused cross-attention
// ---------------------------------------------------------------------------
__global__ void __launch_bounds__(TPB, 2)
cross_attn_kernel(const float* __restrict__ query,
                  const float* __restrict__ ref,
                  const float* __restrict__ W_off,
                  const float* __restrict__ b_off,
                  const float* __restrict__ W_attn,
                  const float* __restrict__ b_attn,
                  const float* __restrict__ W_out,
                  const float* __restrict__ b_out,
                  float* __restrict__ out,
                  float* __restrict__ out_idx,
                  int n_idx) {
    extern __shared__ float sm[];
    float* s_wout = sm;                    // D*D      = 16384
    float* s_msda = s_wout + D * D;        // NL*D     = 6400
    float* s_q    = s_msda + NL * D;       // 128
    float* s_avg  = s_q + D;               // 128
    float* s_off  = s_avg + D;             // 64  (pre-normalized offsets)
    float* s_aw   = s_off + 64;            // 32  (point softmax weights)
    float* s_wp   = s_aw + 32;             // 128
    float* s_wts  = s_wp + D;              // 64  (level logits -> weights)

    int tid = threadIdx.x;
    for (int i = tid; i < D * D; i += TPB) s_wout[i] = W_out[i];
    if (tid < D) s_wp[tid] = g_wp[tid];

    for (int q = blockIdx.x; q < NQ; q += gridDim.x) {
        __syncthreads();                       // protect smem reuse
        if (tid < D) s_q[tid] = query[q * D + tid];
        __syncthreads();

        // ---- offsets (64 cols) + attention logits (32 cols): 96-thread GEMV
        if (tid < 96) {
            bool is_off = tid < 64;
            int col = is_off ? tid : tid - 64;
            const float* W = is_off ? W_off : W_attn;
            const float* b = is_off ? b_off : b_attn;
            int stride = is_off ? 64 : 32;
            float acc = b[col];
#pragma unroll 8
            for (int k = 0; k < D; k++)
                acc = fmaf(s_q[k], W[k * stride + col], acc);
            if (is_off)
                s_off[col] = acc / ((col & 1) ? (float)HSP : (float)WSP);
            else
                s_aw[col] = acc;
        }
        __syncthreads();

        // ---- softmax over 4 points per head
        if (tid < NHEADS) {
            float m = s_aw[tid * 4];
            for (int p = 1; p < 4; p++) m = fmaxf(m, s_aw[tid * 4 + p]);
            float e[4]; float ssum = 0.f;
            for (int p = 0; p < 4; p++) {
                e[p] = expf(s_aw[tid * 4 + p] - m);
                ssum += e[p];
            }
            for (int p = 0; p < 4; p++) s_aw[tid * 4 + p] = e[p] / ssum;
        }
        __syncthreads();

        // ---- MSDA sampling: 1600 units = (level, head, chan4). Warp-uniform l.
        for (int u = tid; u < NL * 32; u += TPB) {
            int l = u >> 5;
            int h = (u >> 2) & 7;
            int c = u & 3;
            float rx = ref[(l * NQ + q) * 2 + 0];
            float ry = ref[(l * NQ + q) * 2 + 1];
            const float* base = g_proj + h * (HW * HD) + c * 4;
            float a0 = 0.f, a1 = 0.f, a2 = 0.f, a3 = 0.f;
#pragma unroll
            for (int p = 0; p < NPOINTS; p++) {
                float aw = s_aw[h * 4 + p];
                float lx = rx + s_off[(h * 4 + p) * 2 + 0];
                float ly = ry + s_off[(h * 4 + p) * 2 + 1];
                float px = lx * (float)WSP - 0.5f;
                float py = ly * (float)HSP - 0.5f;
                float x0f = floorf(px), y0f = floorf(py);
                float dx = px - x0f, dy = py - y0f;
                int x0 = (int)x0f, y0 = (int)y0f;
                bool vx0 = (unsigned)x0 < WSP;
                bool vx1 = (unsigned)(x0 + 1) < WSP;
                bool vy0 = (unsigned)y0 < HSP;
                bool vy1 = (unsigned)(y0 + 1) < HSP;
                float w00 = aw * (1.f - dx) * (1.f - dy);
                float w01 = aw * dx * (1.f - dy);
                float w10 = aw * (1.f - dx) * dy;
                float w11 = aw * dx * dy;
                const float* r0 = base + (y0 * WSP + x0) * HD;
                const float* r1 = r0 + WSP * HD;
                if (vy0 && vx0) { float4 v = *(const float4*)r0;
                    a0 = fmaf(w00, v.x, a0); a1 = fmaf(w00, v.y, a1);
                    a2 = fmaf(w00, v.z, a2); a3 = fmaf(w00, v.w, a3); }
                if (vy0 && vx1) { float4 v = *(const float4*)(r0 + HD);
                    a0 = fmaf(w01, v.x, a0); a1 = fmaf(w01, v.y, a1);
                    a2 = fmaf(w01, v.z, a2); a3 = fmaf(w01, v.w, a3); }
                if (vy1 && vx0) { float4 v = *(const float4*)r1;
                    a0 = fmaf(w10, v.x, a0); a1 = fmaf(w10, v.y, a1);
                    a2 = fmaf(w10, v.z, a2); a3 = fmaf(w10, v.w, a3); }
                if (vy1 && vx1) { float4 v = *(const float4*)(r1 + HD);
                    a0 = fmaf(w11, v.x, a0); a1 = fmaf(w11, v.y, a1);
                    a2 = fmaf(w11, v.z, a2); a3 = fmaf(w11, v.w, a3); }
            }
            int db = l * D + h * HD + c * 4;
            s_msda[db + 0] = a0; s_msda[db + 1] = a1;
            s_msda[db + 2] = a2; s_msda[db + 3] = a3;
        }
        __syncthreads();

        // ---- level logits: logit_l = msda_l . Wp  (softmax-equivalent)
        {
            int warp = tid >> 5, lane = tid & 31;
            for (int l = warp; l < NL; l += 8) {
                float s = 0.f;
#pragma unroll
                for (int j = 0; j < 4; j++)
                    s = fmaf(s_msda[l * D + lane * 4 + j], s_wp[lane * 4 + j], s);
#pragma unroll
                for (int o = 16; o; o >>= 1)
                    s += __shfl_down_sync(0xffffffffu, s, o);
                if (lane == 0) s_wts[l] = s;
            }
        }
        __syncthreads();

        // ---- level softmax + argmax (thread 0, 50 elems)
        if (tid == 0) {
            float m = s_wts[0]; int am = 0;
            for (int l = 1; l < NL; l++) {
                float v = s_wts[l];
                if (v > m) { m = v; am = l; }
            }
            float ssum = 0.f;
            for (int l = 0; l < NL; l++) {
                float e = expf(s_wts[l] - m);
                s_wts[l] = e; ssum += e;
            }
            float inv = 1.f / ssum;
            for (int l = 0; l < NL; l++) s_wts[l] *= inv;
            if (q < n_idx) out_idx[q] = (float)am;
        }
        __syncthreads();

        // ---- weighted average over levels
        if (tid < D) {
            float acc = 0.f;
            for (int l = 0; l < NL; l++)
                acc = fmaf(s_wts[l], s_msda[l * D + tid], acc);
            s_avg[tid] = acc;
        }
        __syncthreads();

        // ---- final: out = avg @ W_out + b_out + 2*query
        if (tid < D) {
            float acc = fmaf(2.0f, s_q[tid], b_out[tid]);
#pragma unroll 8
            for (int k = 0; k < D; k++)
                acc = fmaf(s_avg[k], s_wout[k * D + tid], acc);
            out[q * D + tid] = acc;
        }
    }
}

// ---------------------------------------------------------------------------
extern "C" void kernel_launch(void* const* d_in, const int* in_sizes, int n_in,
                              void* d_out, int out_size) {
    const float* query  = (const float*)d_in[0];
    const float* value  = (const float*)d_in[1];
    const float* refp   = (const float*)d_in[2];
    const float* W_off  = (const float*)d_in[3];
    const float* b_off  = (const float*)d_in[4];
    const float* W_attn = (const float*)d_in[5];
    const float* b_attn = (const float*)d_in[6];
    const float* W_val  = (const float*)d_in[7];
    const float* b_val  = (const float*)d_in[8];
    const float* W_out  = (const float*)d_in[9];
    const float* b_out  = (const float*)d_in[10];
    const float* W_proj = (const float*)d_in[11];
    // b_proj (d_in[12]) unused: constant shift is softmax/argmax-invariant.

    float* out = (float*)d_out;

    int n_idx = out_size - NQ * D;           // extra slots beyond bev output
    if (n_idx < 0) n_idx = 0;
    if (n_idx > NQ) n_idx = NQ;

    size_t smem = (size_t)(D * D + NL * D + D + D + 64 + 32 + D + 64) * sizeof(float);
    cudaFuncSetAttribute(cross_attn_kernel,
                         cudaFuncAttributeMaxDynamicSharedMemorySize, (int)smem);

    val_proj_kernel<<<(HW + 63) / 64, D>>>(value, W_val, b_val);
    wp_kernel<<<1, D>>>(W_out, W_proj);
    cross_attn_kernel<<<GRID, TPB, smem>>>(query, refp, W_off, b_off,
                                           W_attn, b_attn, W_out, b_out,
                                           out, out + NQ * D, n_idx);

    int tail = out_size - (NQ * D + NQ);
    if (tail > 0)
        fill_zero_kernel<<<(tail + 255) / 256, 256>>>(out + NQ * D + NQ, tail);
}

// round 3
// speedup vs baseline: 1.6014x; 1.6014x over previous
#include <cuda_runtime.h>

#define NQ      10000
#define D       128
#define NHEADS  8
#define NPOINTS 4
#define HSP     51
#define WSP     102
#define HW      (HSP * WSP)
#define NL      50
#define HD      16
#define TPB     256
#define GRID    592

// Scratch (device globals; no allocation allowed)
__device__ float g_proj[NHEADS * HW * HD];   // [head][spatial][hd-chan], 2.66 MB
__device__ float g_wp[D];                    // W_out @ W_proj (128-vector)

// ---------------------------------------------------------------------------
// Kernel A: value projection  v = value @ W_val + b_val, stored head-major
// 32 spatial rows per block; W k-tiles staged transposed through smem.
// ---------------------------------------------------------------------------
__global__ void __launch_bounds__(TPB, 2)
val_proj_kernel(const float* __restrict__ value,
                const float* __restrict__ W_val,
                const float* __restrict__ b_val) {
    __shared__ float s_val[32 * D];          // 16 KB
    __shared__ float s_wT[D * 33];           // transposed W k-tile, padded

    int tid = threadIdx.x;
    int row0 = blockIdx.x * 32;
    int d = tid & 127;
    int rbase = tid >> 7;                    // 0 or 1

    // load 32 value rows (zero-padded at tail)
    for (int i = tid; i < 32 * D; i += TPB) {
        int s = row0 + (i >> 7);
        s_val[i] = (s < HW) ? value[s * D + (i & 127)] : 0.f;
    }

    float acc[16];
#pragma unroll
    for (int i = 0; i < 16; i++) acc[i] = 0.f;

    for (int kt = 0; kt < 4; kt++) {
        __syncthreads();
        // stage W rows [kt*32, kt*32+32) transposed: s_wT[d][kk]
        for (int i = tid; i < 32 * D; i += TPB) {
            int kk = i >> 7, dd = i & 127;
            s_wT[dd * 33 + kk] = W_val[(kt * 32 + kk) * D + dd];
        }
        __syncthreads();

        float w[32];
#pragma unroll
        for (int kk = 0; kk < 32; kk++) w[kk] = s_wT[d * 33 + kk];

#pragma unroll
        for (int ri = 0; ri < 16; ri++) {
            int r = rbase + ri * 2;
            const float4* vrow = (const float4*)&s_val[r * D + kt * 32];
            float a = acc[ri];
#pragma unroll
            for (int k4 = 0; k4 < 8; k4++) {
                float4 v = vrow[k4];
                a = fmaf(v.x, w[k4 * 4 + 0], a);
                a = fmaf(v.y, w[k4 * 4 + 1], a);
                a = fmaf(v.z, w[k4 * 4 + 2], a);
                a = fmaf(v.w, w[k4 * 4 + 3], a);
            }
            acc[ri] = a;
        }
    }

    float bv = b_val[d];
    int h = d >> 4, c = d & 15;
#pragma unroll
    for (int ri = 0; ri < 16; ri++) {
        int s = row0 + rbase + ri * 2;
        if (s < HW)
            g_proj[h * (HW * HD) + s * HD + c] = acc[ri] + bv;
    }
}

// ---------------------------------------------------------------------------
// Kernel B: Wp[k] = sum_d W_out[k][d] * W_proj[d]
// ---------------------------------------------------------------------------
__global__ void wp_kernel(const float* __restrict__ W_out,
                          const float* __restrict__ W_proj) {
    int k = threadIdx.x;
    float acc = 0.f;
#pragma unroll 8
    for (int dd = 0; dd < D; dd++)
        acc = fmaf(W_out[k * D + dd], W_proj[dd], acc);
    g_wp[k] = acc;
}

// ---------------------------------------------------------------------------
__global__ void fill_zero_kernel(float* __restrict__ p, int n) {
    int i = blockIdx.x * 256 + threadIdx.x;
    if (i < n) p[i] = 0.f;
}

// ---------------------------------------------------------------------------
// Kernel C: main fused cross-attention
// ---------------------------------------------------------------------------
__global__ void __launch_bounds__(TPB, 4)
cross_attn_kernel(const float* __restrict__ query,
                  const float* __restrict__ ref,
                  const float* __restrict__ W_off,
                  const float* __restrict__ b_off,
                  const float* __restrict__ W_attn,
                  const float* __restrict__ b_attn,
                  const float* __restrict__ W_out,
                  const float* __restrict__ b_out,
                  float* __restrict__ out,
                  float* __restrict__ out_idx,
                  int n_idx) {
    __shared__ float s_msda[NL * D];     // 25.6 KB
    __shared__ float s_q[D];
    __shared__ float s_avg[D];
    __shared__ float s_off[64];
    __shared__ float s_aw[32];
    __shared__ float s_wp[D];
    __shared__ float s_wts[64];
    __shared__ float s_ref[104];
    __shared__ float s_part[D];

    const float* __restrict__ proj = g_proj;

    int tid = threadIdx.x;
    if (tid < D) s_wp[tid] = g_wp[tid];

    for (int q = blockIdx.x; q < NQ; q += gridDim.x) {
        __syncthreads();                     // protect smem reuse
        if (tid < D) s_q[tid] = query[q * D + tid];
        __syncthreads();

        // ---- offsets (64 cols) + attn logits (32 cols): 192-thread k-split GEMV
        //      warps 6-7 concurrently preload ref pairs for all 50 levels
        if (tid < 192) {
            int col = tid >> 1;
            int half = tid & 1;
            bool is_off = col < 64;
            const float* W = is_off ? (W_off + col) : (W_attn + (col - 64));
            int stride = is_off ? 64 : 32;
            float acc = 0.f;
            if (half == 0)
                acc = is_off ? b_off[col] : b_attn[col - 64];
            int k0 = half * 64;
#pragma unroll 8
            for (int k = 0; k < 64; k++)
                acc = fmaf(s_q[k0 + k], W[(k0 + k) * stride], acc);
            acc += __shfl_xor_sync(0xffffffffu, acc, 1);
            if (half == 0) {
                if (is_off)
                    s_off[col] = acc / ((col & 1) ? (float)HSP : (float)WSP);
                else
                    s_aw[col - 64] = acc;
            }
        } else {
            for (int i = tid - 192; i < 2 * NL; i += 64)
                s_ref[i] = ref[(i >> 1) * (NQ * 2) + q * 2 + (i & 1)];
        }
        __syncthreads();

        // ---- softmax over 4 points per head
        if (tid < NHEADS) {
            float m = s_aw[tid * 4];
#pragma unroll
            for (int p = 1; p < 4; p++) m = fmaxf(m, s_aw[tid * 4 + p]);
            float e[4]; float ssum = 0.f;
#pragma unroll
            for (int p = 0; p < 4; p++) {
                e[p] = expf(s_aw[tid * 4 + p] - m);
                ssum += e[p];
            }
            float inv = 1.f / ssum;
#pragma unroll
            for (int p = 0; p < 4; p++) s_aw[tid * 4 + p] = e[p] * inv;
        }
        __syncthreads();

        // ---- MSDA sampling: 1600 units = (level, head, chan4). Warp-uniform l.
        for (int u = tid; u < NL * 32; u += TPB) {
            int l = u >> 5;
            int h = (u >> 2) & 7;
            int c = u & 3;
            float rx = s_ref[l * 2 + 0];
            float ry = s_ref[l * 2 + 1];
            const float* base = proj + h * (HW * HD) + c * 4;
            float a0 = 0.f, a1 = 0.f, a2 = 0.f, a3 = 0.f;
#pragma unroll
            for (int p = 0; p < NPOINTS; p++) {
                float aw = s_aw[h * 4 + p];
                float lx = rx + s_off[(h * 4 + p) * 2 + 0];
                float ly = ry + s_off[(h * 4 + p) * 2 + 1];
                float px = lx * (float)WSP - 0.5f;
                float py = ly * (float)HSP - 0.5f;
                float x0f = floorf(px), y0f = floorf(py);
                float dx = px - x0f, dy = py - y0f;
                int x0 = (int)x0f, y0 = (int)y0f;
                bool vx0 = (unsigned)x0 < WSP;
                bool vx1 = (unsigned)(x0 + 1) < WSP;
                bool vy0 = (unsigned)y0 < HSP;
                bool vy1 = (unsigned)(y0 + 1) < HSP;
                float w00 = aw * (1.f - dx) * (1.f - dy);
                float w01 = aw * dx * (1.f - dy);
                float w10 = aw * (1.f - dx) * dy;
                float w11 = aw * dx * dy;
                const float* r0 = base + (y0 * WSP + x0) * HD;
                const float* r1 = r0 + WSP * HD;
                if (vy0 && vx0) { float4 v = *(const float4*)r0;
                    a0 = fmaf(w00, v.x, a0); a1 = fmaf(w00, v.y, a1);
                    a2 = fmaf(w00, v.z, a2); a3 = fmaf(w00, v.w, a3); }
                if (vy0 && vx1) { float4 v = *(const float4*)(r0 + HD);
                    a0 = fmaf(w01, v.x, a0); a1 = fmaf(w01, v.y, a1);
                    a2 = fmaf(w01, v.z, a2); a3 = fmaf(w01, v.w, a3); }
                if (vy1 && vx0) { float4 v = *(const float4*)r1;
                    a0 = fmaf(w10, v.x, a0); a1 = fmaf(w10, v.y, a1);
                    a2 = fmaf(w10, v.z, a2); a3 = fmaf(w10, v.w, a3); }
                if (vy1 && vx1) { float4 v = *(const float4*)(r1 + HD);
                    a0 = fmaf(w11, v.x, a0); a1 = fmaf(w11, v.y, a1);
                    a2 = fmaf(w11, v.z, a2); a3 = fmaf(w11, v.w, a3); }
            }
            int db = l * D + h * HD + c * 4;
            s_msda[db + 0] = a0; s_msda[db + 1] = a1;
            s_msda[db + 2] = a2; s_msda[db + 3] = a3;
        }
        __syncthreads();

        // ---- level logits: logit_l = msda_l . Wp
        {
            int warp = tid >> 5, lane = tid & 31;
            for (int l = warp; l < NL; l += 8) {
                float s = 0.f;
#pragma unroll
                for (int j = 0; j < 4; j++)
                    s = fmaf(s_msda[l * D + lane * 4 + j], s_wp[lane * 4 + j], s);
#pragma unroll
                for (int o = 16; o; o >>= 1)
                    s += __shfl_down_sync(0xffffffffu, s, o);
                if (lane == 0) s_wts[l] = s;
            }
        }
        __syncthreads();

        // ---- level softmax + argmax: warp 0, parallel
        if (tid < 32) {
            float v0 = (tid < NL) ? s_wts[tid] : -3.4e38f;
            float v1 = (tid + 32 < NL) ? s_wts[tid + 32] : -3.4e38f;
            float bv; int bi;
            if (v1 > v0) { bv = v1; bi = tid + 32; }
            else         { bv = v0; bi = tid; }
#pragma unroll
            for (int o = 16; o; o >>= 1) {
                float ov = __shfl_down_sync(0xffffffffu, bv, o);
                int   oi = __shfl_down_sync(0xffffffffu, bi, o);
                if (ov > bv || (ov == bv && oi < bi)) { bv = ov; bi = oi; }
            }
            bv = __shfl_sync(0xffffffffu, bv, 0);       // broadcast max
            float e0 = (tid < NL) ? expf(v0 - bv) : 0.f;
            float e1 = (tid + 32 < NL) ? expf(v1 - bv) : 0.f;
            float ssum = e0 + e1;
#pragma unroll
            for (int o = 16; o; o >>= 1)
                ssum += __shfl_xor_sync(0xffffffffu, ssum, o);
            float inv = 1.f / ssum;
            if (tid < NL) s_wts[tid] = e0 * inv;
            if (tid + 32 < NL) s_wts[tid + 32] = e1 * inv;
            if (tid == 0 && q < n_idx) out_idx[q] = (float)bi;
        }
        __syncthreads();

        // ---- weighted average over levels
        if (tid < D) {
            float acc = 0.f;
#pragma unroll 5
            for (int l = 0; l < NL; l++)
                acc = fmaf(s_wts[l], s_msda[l * D + tid], acc);
            s_avg[tid] = acc;
        }
        __syncthreads();

        // ---- final: out = avg @ W_out + b_out + 2*query   (k-split, 256 thr)
        {
            int ch = tid & 127, half = tid >> 7;
            int k0 = half * 64;
            float acc = 0.f;
#pragma unroll 8
            for (int k = 0; k < 64; k++)
                acc = fmaf(s_avg[k0 + k], W_out[(k0 + k) * D + ch], acc);
            if (half) s_part[ch] = acc;
            __syncthreads();
            if (!half)
                out[q * D + ch] = acc + s_part[ch] + b_out[ch]
                                  + fmaf(2.0f, s_q[ch], 0.f);
        }
    }
}

// ---------------------------------------------------------------------------
extern "C" void kernel_launch(void* const* d_in, const int* in_sizes, int n_in,
                              void* d_out, int out_size) {
    const float* query  = (const float*)d_in[0];
    const float* value  = (const float*)d_in[1];
    const float* refp   = (const float*)d_in[2];
    const float* W_off  = (const float*)d_in[3];
    const float* b_off  = (const float*)d_in[4];
    const float* W_attn = (const float*)d_in[5];
    const float* b_attn = (const float*)d_in[6];
    const float* W_val  = (const float*)d_in[7];
    const float* b_val  = (const float*)d_in[8];
    const float* W_out  = (const float*)d_in[9];
    const float* b_out  = (const float*)d_in[10];
    const float* W_proj = (const float*)d_in[11];
    // b_proj (d_in[12]) unused: constant shift is softmax/argmax-invariant.

    float* out = (float*)d_out;

    int n_idx = out_size - NQ * D;           // extra slots beyond bev output
    if (n_idx < 0) n_idx = 0;
    if (n_idx > NQ) n_idx = NQ;

    val_proj_kernel<<<(HW + 31) / 32, TPB>>>(value, W_val, b_val);
    wp_kernel<<<1, D>>>(W_out, W_proj);
    cross_attn_kernel<<<GRID, TPB>>>(query, refp, W_off, b_off,
                                     W_attn, b_attn, W_out, b_out,
                                     out, out + NQ * D, n_idx);

    int tail = out_size - (NQ * D + NQ);
    if (tail > 0)
        fill_zero_kernel<<<(tail + 255) / 256, 256>>>(out + NQ * D + NQ, tail);
}

// round 4
// speedup vs baseline: 1.7040x; 1.0641x over previous
#include <cuda_runtime.h>

#define NQ      10000
#define D       128
#define NHEADS  8
#define NPOINTS 4
#define HSP     51
#define WSP     102
#define HW      (HSP * WSP)
#define NL      50
#define HD      16
#define TPB     256
#define GRID    592

// Scratch (device globals; no allocation allowed)
__device__ float g_proj[NHEADS * HW * HD];   // [head][spatial][16ch], 2.66 MB
__device__ unsigned g_arrive = 0;
__device__ unsigned g_depart = 0;

// ---------------------------------------------------------------------------
// Fused persistent kernel:
//   phase 0: value projection (all blocks, strided rows) + output tail zero
//   device-wide barrier (all 592 blocks co-resident: 148 SMs x occupancy 4)
//   phase 1: per-query deformable attention, level softmax, final GEMV
// ---------------------------------------------------------------------------
__global__ void __launch_bounds__(TPB, 4)
fused_kernel(const float* __restrict__ query,
             const float* __restrict__ value,
             const float* __restrict__ ref,
             const float* __restrict__ W_off,
             const float* __restrict__ b_off,
             const float* __restrict__ W_attn,
             const float* __restrict__ b_attn,
             const float* __restrict__ W_val,
             const float* __restrict__ b_val,
             const float* __restrict__ W_out,
             const float* __restrict__ b_out,
             const float* __restrict__ W_proj,
             float* __restrict__ out,
             float* __restrict__ out_idx,
             int n_idx,
             float* __restrict__ tailp,
             int tail_n) {
    __shared__ float s_msda[NL * D];     // 25.6 KB
    __shared__ float s_q[D];
    __shared__ float s_avg[D];
    __shared__ float s_off[64];          // pre-normalized offsets (x,y per h,p)
    __shared__ float s_aw[32];           // point softmax weights
    __shared__ float s_wp[D];            // W_out @ W_proj
    __shared__ float s_wts[64];          // level logits -> weights
    __shared__ float s_refy[NL];
    __shared__ float s_refx;
    __shared__ float s_part[D];
    __shared__ float s_wx[64];           // masked x-corner weights per (h,p)
    __shared__ int   s_cx[64];           // clamped x-corner coords per (h,p)
    __shared__ float s_val[2 * D];       // phase-0 staging

    const float* __restrict__ proj = g_proj;
    int tid = threadIdx.x;

    // ===================== phase 0: value projection ========================
    {
        int ch = tid & 127;
        int half = tid >> 7;
        for (int s0 = blockIdx.x * 2; s0 < HW; s0 += GRID * 2) {
            int s = s0 + half;
            bool ok = s < HW;
            __syncthreads();
            if (ok) s_val[half * D + ch] = value[s * D + ch];
            __syncthreads();
            if (ok) {
                float acc = b_val[ch];
                const float* vr = &s_val[half * D];
#pragma unroll 8
                for (int k = 0; k < D; k++)
                    acc = fmaf(vr[k], W_val[k * D + ch], acc);
                g_proj[(ch >> 4) * (HW * HD) + s * HD + (ch & 15)] = acc;
            }
        }
        // zero output tail (if any) while we're here
        for (int i = blockIdx.x * TPB + tid; i < tail_n; i += GRID * TPB)
            tailp[i] = 0.f;
    }

    // ===================== device-wide barrier ==============================
    __syncthreads();
    if (tid == 0) {
        __threadfence();
        atomicAdd(&g_arrive, 1u);
        while (*(volatile unsigned*)&g_arrive < GRID) { }
        __threadfence();
        unsigned old = atomicAdd(&g_depart, 1u);
        if (old == GRID - 1) {
            *(volatile unsigned*)&g_arrive = 0u;
            __threadfence();
            *(volatile unsigned*)&g_depart = 0u;
        }
    }
    __syncthreads();

    // ===================== wp = W_out @ W_proj (per block, coalesced) =======
    {
        if (tid < D) s_wts[0] = 0.f;           // noop keep
        if (tid < D) s_avg[tid] = W_proj[tid]; // stage W_proj
        __syncthreads();
        int warp = tid >> 5, lane = tid & 31;
        for (int r = warp; r < D; r += 8) {
            float a = 0.f;
#pragma unroll
            for (int kk = 0; kk < 4; kk++) {
                int k = lane + kk * 32;
                a = fmaf(W_out[r * D + k], s_avg[k], a);
            }
#pragma unroll
            for (int o = 16; o; o >>= 1)
                a += __shfl_down_sync(0xffffffffu, a, o);
            if (lane == 0) s_wp[r] = a;
        }
    }

    // ===================== phase 1: per-query attention =====================
    for (int q = blockIdx.x; q < NQ; q += GRID) {
        __syncthreads();                     // protect smem reuse
        if (tid < D) s_q[tid] = query[q * D + tid];
        __syncthreads();

        // ---- offsets (64) + attn logits (32): 192-thread k-split GEMV;
        //      warps 6-7 concurrently load ref y per level (+ level-0 x)
        if (tid < 192) {
            int col = tid >> 1;
            int half = tid & 1;
            bool is_off = col < 64;
            const float* W = is_off ? (W_off + col) : (W_attn + (col - 64));
            int stride = is_off ? 64 : 32;
            float acc = 0.f;
            if (half == 0)
                acc = is_off ? b_off[col] : b_attn[col - 64];
            int k0 = half * 64;
#pragma unroll 8
            for (int k = 0; k < 64; k++)
                acc = fmaf(s_q[k0 + k], W[(k0 + k) * stride], acc);
            acc += __shfl_xor_sync(0xffffffffu, acc, 1);
            if (half == 0) {
                if (is_off)
                    s_off[col] = acc / ((col & 1) ? (float)HSP : (float)WSP);
                else
                    s_aw[col - 64] = acc;
            }
        } else {
            int i = tid - 192;
            if (i < NL)
                s_refy[i] = ref[i * (NQ * 2) + q * 2 + 1];
            else if (i == NL)
                s_refx = ref[q * 2 + 0];     // phi is z-invariant: same all levels
        }
        __syncthreads();

        // ---- point softmax (tid<8) + level-invariant x precompute (tid 32..63)
        if (tid < NHEADS) {
            float m = s_aw[tid * 4];
#pragma unroll
            for (int p = 1; p < 4; p++) m = fmaxf(m, s_aw[tid * 4 + p]);
            float e[4]; float ssum = 0.f;
#pragma unroll
            for (int p = 0; p < 4; p++) {
                e[p] = expf(s_aw[tid * 4 + p] - m);
                ssum += e[p];
            }
            float inv = 1.f / ssum;
#pragma unroll
            for (int p = 0; p < 4; p++) s_aw[tid * 4 + p] = e[p] * inv;
        } else if (tid >= 32 && tid < 64) {
            int up = tid - 32;               // (h,p) unit
            float px = (s_refx + s_off[up * 2]) * (float)WSP - 0.5f;
            float x0f = floorf(px);
            float dx = px - x0f;
            int x0 = (int)x0f;
            s_wx[up * 2 + 0] = ((unsigned)x0 < WSP) ? (1.f - dx) : 0.f;
            s_wx[up * 2 + 1] = ((unsigned)(x0 + 1) < WSP) ? dx : 0.f;
            s_cx[up * 2 + 0] = min(max(x0, 0), WSP - 1);
            s_cx[up * 2 + 1] = min(max(x0 + 1, 0), WSP - 1);
        }
        __syncthreads();

        // ---- MSDA sampling: unit = (level, head), 8 lanes per unit.
        //      lanes 0-3: corner x0 (4 ch each), lanes 4-7: corner x1.
        //      Interior case: each unit's row-load = 128B contiguous.
        {
            int j = tid & 7;
            int slot = tid >> 3;             // 0..31
            int xc_off = (j >> 2) & 1;
            int cidx = (j & 3) * 4;
            for (int u = slot; u < NL * NHEADS; u += 32) {
                int l = u >> 3, h = u & 7;
                float ry = s_refy[l];
                const float* basep = proj + h * (HW * HD) + cidx;
                float a0 = 0.f, a1 = 0.f, a2 = 0.f, a3 = 0.f;
#pragma unroll
                for (int p = 0; p < NPOINTS; p++) {
                    int up = h * 4 + p;
                    float py = (ry + s_off[up * 2 + 1]) * (float)HSP - 0.5f;
                    float y0f = floorf(py);
                    float dy = py - y0f;
                    int y0 = (int)y0f;
                    float wy0 = ((unsigned)y0 < HSP) ? (1.f - dy) : 0.f;
                    float wy1 = ((unsigned)(y0 + 1) < HSP) ? dy : 0.f;
                    int cy0 = min(max(y0, 0), HSP - 1);
                    int cy1 = min(max(y0 + 1, 0), HSP - 1);
                    float waw = s_wx[up * 2 + xc_off] * s_aw[up];
                    int xc = s_cx[up * 2 + xc_off];
                    const float4* p0 = (const float4*)(basep + (cy0 * WSP + xc) * HD);
                    const float4* p1 = (const float4*)(basep + (cy1 * WSP + xc) * HD);
                    float4 v0 = *p0;
                    float4 v1 = *p1;
                    float w0 = waw * wy0, w1 = waw * wy1;
                    a0 = fmaf(w0, v0.x, fmaf(w1, v1.x, a0));
                    a1 = fmaf(w0, v0.y, fmaf(w1, v1.y, a1));
                    a2 = fmaf(w0, v0.z, fmaf(w1, v1.z, a2));
                    a3 = fmaf(w0, v0.w, fmaf(w1, v1.w, a3));
                }
                // combine x0/x1 corner halves (lanes j and j^4)
                a0 += __shfl_xor_sync(0xffffffffu, a0, 4);
                a1 += __shfl_xor_sync(0xffffffffu, a1, 4);
                a2 += __shfl_xor_sync(0xffffffffu, a2, 4);
                a3 += __shfl_xor_sync(0xffffffffu, a3, 4);
                if (j < 4) {
                    float4 r; r.x = a0; r.y = a1; r.z = a2; r.w = a3;
                    *(float4*)&s_msda[l * D + h * HD + cidx] = r;
                }
            }
        }
        __syncthreads();

        // ---- level logits: logit_l = msda_l . wp
        {
            int warp = tid >> 5, lane = tid & 31;
            for (int l = warp; l < NL; l += 8) {
                float s = 0.f;
#pragma unroll
                for (int jj = 0; jj < 4; jj++)
                    s = fmaf(s_msda[l * D + lane * 4 + jj], s_wp[lane * 4 + jj], s);
#pragma unroll
                for (int o = 16; o; o >>= 1)
                    s += __shfl_down_sync(0xffffffffu, s, o);
                if (lane == 0) s_wts[l] = s;
            }
        }
        __syncthreads();

        // ---- level softmax + argmax: warp 0, parallel
        if (tid < 32) {
            float v0 = (tid < NL) ? s_wts[tid] : -3.4e38f;
            float v1 = (tid + 32 < NL) ? s_wts[tid + 32] : -3.4e38f;
            float bv; int bi;
            if (v1 > v0) { bv = v1; bi = tid + 32; }
            else         { bv = v0; bi = tid; }
#pragma unroll
            for (int o = 16; o; o >>= 1) {
                float ov = __shfl_down_sync(0xffffffffu, bv, o);
                int   oi = __shfl_down_sync(0xffffffffu, bi, o);
                if (ov > bv || (ov == bv && oi < bi)) { bv = ov; bi = oi; }
            }
            bv = __shfl_sync(0xffffffffu, bv, 0);
            float e0 = (tid < NL) ? expf(v0 - bv) : 0.f;
            float e1 = (tid + 32 < NL) ? expf(v1 - bv) : 0.f;
            float ssum = e0 + e1;
#pragma unroll
            for (int o = 16; o; o >>= 1)
                ssum += __shfl_xor_sync(0xffffffffu, ssum, o);
            float inv = 1.f / ssum;
            if (tid < NL) s_wts[tid] = e0 * inv;
            if (tid + 32 < NL) s_wts[tid + 32] = e1 * inv;
            if (tid == 0 && q < n_idx) out_idx[q] = (float)bi;
        }
        __syncthreads();

        // ---- weighted average over levels
        if (tid < D) {
            float acc = 0.f;
#pragma unroll 5
            for (int l = 0; l < NL; l++)
                acc = fmaf(s_wts[l], s_msda[l * D + tid], acc);
            s_avg[tid] = acc;
        }
        __syncthreads();

        // ---- final: out = avg @ W_out + b_out + 2*query   (k-split, 256 thr)
        {
            int ch = tid & 127, half = tid >> 7;
            int k0 = half * 64;
            float acc = 0.f;
#pragma unroll 8
            for (int k = 0; k < 64; k++)
                acc = fmaf(s_avg[k0 + k], W_out[(k0 + k) * D + ch], acc);
            if (half) s_part[ch] = acc;
            __syncthreads();
            if (!half)
                out[q * D + ch] = acc + s_part[ch] + b_out[ch] + 2.0f * s_q[ch];
        }
    }
}

// ---------------------------------------------------------------------------
extern "C" void kernel_launch(void* const* d_in, const int* in_sizes, int n_in,
                              void* d_out, int out_size) {
    const float* query  = (const float*)d_in[0];
    const float* value  = (const float*)d_in[1];
    const float* refp   = (const float*)d_in[2];
    const float* W_off  = (const float*)d_in[3];
    const float* b_off  = (const float*)d_in[4];
    const float* W_attn = (const float*)d_in[5];
    const float* b_attn = (const float*)d_in[6];
    const float* W_val  = (const float*)d_in[7];
    const float* b_val  = (const float*)d_in[8];
    const float* W_out  = (const float*)d_in[9];
    const float* b_out  = (const float*)d_in[10];
    const float* W_proj = (const float*)d_in[11];
    // b_proj (d_in[12]) unused: constant shift is softmax/argmax-invariant.

    float* out = (float*)d_out;

    int n_idx = out_size - NQ * D;           // extra slots beyond bev output
    if (n_idx < 0) n_idx = 0;
    if (n_idx > NQ) n_idx = NQ;

    int tail_n = out_size - (NQ * D + NQ);
    float* tailp = out + NQ * D + NQ;
    if (tail_n < 0) { tail_n = 0; tailp = out; }

    fused_kernel<<<GRID, TPB>>>(query, value, refp, W_off, b_off,
                                W_attn, b_attn, W_val, b_val,
                                W_out, b_out, W_proj,
                                out, out + NQ * D, n_idx, tailp, tail_n);
}